// round 12
// baseline (speedup 1.0000x reference)
#include <cuda_runtime.h>
#include <cuda_bf16.h>
#include <cstdint>
#include <math.h>

#define ITEM_NUM 50000
#define BATCH    4096
#define HIST     50
#define KN       10

#define TBM      128               // main kernel threads (4 warps)
#define CTAS_SM  4
#define GRIDM    (148 * CTAS_SM)   // 592
#define MROWS    64                // M tile (1 batch element, 50 valid rows)

#define PITCH_F  272               // fp8 pitch (68 words = 4 mod 32 banks)

#define SCALE_X  4096.0f           // 2^12
#define SCALE_W  256.0f            // 2^8
#define INV_SCALE 9.5367431640625e-7f   // 2^-20
#define INV_DOT   2.44140625e-4f        // 2^-12 (dots column scale)

#define CONV_BLKS   500
#define REGION_BLKS (ITEM_NUM / 4)  // 12500
#define PREP2_GRID  (REGION_BLKS + CONV_BLKS)

// ---------------- device scratch ----------------
__device__ __nv_bfloat16 g_Ein_h  [ITEM_NUM * 64];
__device__ __nv_bfloat16 g_Eout_h [ITEM_NUM * 64];
__device__ __nv_bfloat16 g_Ehist_h[ITEM_NUM * 128];
__device__ __nv_bfloat16 g_Etarg_h[ITEM_NUM * 128];
__device__ __nv_bfloat16 g_rin_h  [ITEM_NUM * 64];
__device__ __nv_bfloat16 g_rout_h [ITEM_NUM * 64];
__device__ uint32_t      g_W8     [128 * 256 / 4];   // fp8-packed W1 * 2^8

// ---------------- PTX helpers ----------------
__device__ __forceinline__ uint32_t smem_u32(const void* p) {
    uint32_t a;
    asm("{ .reg .u64 t; cvta.to.shared.u64 t, %1; cvt.u32.u64 %0, t; }" : "=r"(a) : "l"(p));
    return a;
}

__device__ __forceinline__ void ldmatrix_x4(uint32_t& r0, uint32_t& r1,
                                            uint32_t& r2, uint32_t& r3,
                                            uint32_t addr) {
    asm volatile("ldmatrix.sync.aligned.m8n8.x4.shared.b16 {%0,%1,%2,%3}, [%4];"
                 : "=r"(r0), "=r"(r1), "=r"(r2), "=r"(r3) : "r"(addr));
}

__device__ __forceinline__ void mma_fp8(float& d0, float& d1, float& d2, float& d3,
                                        uint32_t a0, uint32_t a1, uint32_t a2, uint32_t a3,
                                        uint32_t b0, uint32_t b1) {
    asm volatile(
        "mma.sync.aligned.m16n8k32.row.col.f32.e4m3.e4m3.f32 "
        "{%0,%1,%2,%3}, {%4,%5,%6,%7}, {%8,%9}, {%0,%1,%2,%3};"
        : "+f"(d0), "+f"(d1), "+f"(d2), "+f"(d3)
        : "r"(a0), "r"(a1), "r"(a2), "r"(a3), "r"(b0), "r"(b1));
}

__device__ __forceinline__ uint32_t pack4_e4m3(float f0, float f1, float f2, float f3) {
    uint16_t lo, hi;
    asm("cvt.rn.satfinite.e4m3x2.f32 %0, %1, %2;" : "=h"(lo) : "f"(f1), "f"(f0));
    asm("cvt.rn.satfinite.e4m3x2.f32 %0, %1, %2;" : "=h"(hi) : "f"(f3), "f"(f2));
    return (uint32_t)lo | ((uint32_t)hi << 16);
}

__device__ __forceinline__ uint2 f4_to_bf4(float4 a) {
    __nv_bfloat162 p0 = __floats2bfloat162_rn(a.x, a.y);
    __nv_bfloat162 p1 = __floats2bfloat162_rn(a.z, a.w);
    uint2 u;
    u.x = *reinterpret_cast<uint32_t*>(&p0);
    u.y = *reinterpret_cast<uint32_t*>(&p1);
    return u;
}

// unpack bf16x2 word -> float2
__device__ __forceinline__ float2 bf2f(uint32_t w) {
    return __bfloat1622float2(*reinterpret_cast<__nv_bfloat162*>(&w));
}

// 16 bf16 (two uint4) * 16 fp32 targ -> fp8x16 (uint4); NO dot accumulation
__device__ __forceinline__ void mul16_store(uint4 u0, uint4 u1, const float* tg,
                                            void* dst) {
    float x[16];
    const __nv_bfloat162* b0 = reinterpret_cast<const __nv_bfloat162*>(&u0);
    const __nv_bfloat162* b1 = reinterpret_cast<const __nv_bfloat162*>(&u1);
    #pragma unroll
    for (int i = 0; i < 4; i++) {
        float2 f = __bfloat1622float2(b0[i]);
        x[2 * i]     = f.x * tg[2 * i];
        x[2 * i + 1] = f.y * tg[2 * i + 1];
    }
    #pragma unroll
    for (int i = 0; i < 4; i++) {
        float2 f = __bfloat1622float2(b1[i]);
        x[8 + 2 * i]     = f.x * tg[8 + 2 * i];
        x[8 + 2 * i + 1] = f.y * tg[8 + 2 * i + 1];
    }
    uint4 o;
    o.x = pack4_e4m3(x[0] * SCALE_X,  x[1] * SCALE_X,  x[2] * SCALE_X,  x[3] * SCALE_X);
    o.y = pack4_e4m3(x[4] * SCALE_X,  x[5] * SCALE_X,  x[6] * SCALE_X,  x[7] * SCALE_X);
    o.z = pack4_e4m3(x[8] * SCALE_X,  x[9] * SCALE_X,  x[10] * SCALE_X, x[11] * SCALE_X);
    o.w = pack4_e4m3(x[12] * SCALE_X, x[13] * SCALE_X, x[14] * SCALE_X, x[15] * SCALE_X);
    *reinterpret_cast<uint4*>(dst) = o;
}

// ---------------- kernel 1: convert E_in / E_out -> bf16 ------------------
__global__ __launch_bounds__(256)
void conv1_kernel(const float* __restrict__ E_in,
                  const float* __restrict__ E_out) {
    int i = blockIdx.x * 256 + threadIdx.x;
    int stride = gridDim.x * 256;
    const float4* in4  = reinterpret_cast<const float4*>(E_in);
    const float4* out4 = reinterpret_cast<const float4*>(E_out);
    uint2* din  = reinterpret_cast<uint2*>(g_Ein_h);
    uint2* dout = reinterpret_cast<uint2*>(g_Eout_h);
    for (int v = i; v < ITEM_NUM * 64 / 4; v += stride) {
        din [v] = f4_to_bf4(in4 [v]);
        dout[v] = f4_to_bf4(out4[v]);
    }
}

// ---------------- kernel 2: conversions FIRST, region attention after ----
__global__ __launch_bounds__(256)
void prep2_kernel(const int*   __restrict__ near_pois,
                  const float* __restrict__ E_hist,
                  const float* __restrict__ E_targ,
                  const float* __restrict__ W1) {
    const int t = threadIdx.x;

    if (blockIdx.x < CONV_BLKS) {
        int i = blockIdx.x * 256 + t;
        int stride = CONV_BLKS * 256;
        const float4* hi4 = reinterpret_cast<const float4*>(E_hist);
        const float4* tg4 = reinterpret_cast<const float4*>(E_targ);
        const float4* w4  = reinterpret_cast<const float4*>(W1);
        uint2* dhi = reinterpret_cast<uint2*>(g_Ehist_h);
        uint2* dtg = reinterpret_cast<uint2*>(g_Etarg_h);
        for (int v = i; v < ITEM_NUM * 128 / 4; v += stride) {
            dhi[v] = f4_to_bf4(hi4[v]);
            dtg[v] = f4_to_bf4(tg4[v]);
        }
        for (int v = i; v < 128 * 256 / 4; v += stride) {
            float4 a = w4[v];
            g_W8[v] = pack4_e4m3(a.x * SCALE_W, a.y * SCALE_W,
                                 a.z * SCALE_W, a.w * SCALE_W);
        }
        return;
    }

    // ---- region part: bf16-resident smem ----
    __shared__ uint32_t in_su [4][320];
    __shared__ uint32_t out_su[4][320];
    __shared__ float    wo_s  [4][10];
    __shared__ float    wi_s  [4][10];
    __shared__ int      idx_s [4][10];

    const int wid  = t >> 5;
    const int lane = t & 31;
    const int nb   = (blockIdx.x - CONV_BLKS) * 4;

    if (t < 40) idx_s[t / 10][t % 10] = near_pois[(nb + t / 10) * KN + t % 10];
    __syncthreads();

    #pragma unroll
    for (int w = 0; w < 3; w++) {
        int v = t + w * 256;
        if (v < 640) {
            int it = v / 160;
            int r0 = v - it * 160;
            int tb = (r0 >= 80) ? 1 : 0;
            int rr = r0 - tb * 80;
            int k = rr >> 3, c = rr & 7;
            int idx = idx_s[it][k];
            uint4 u = reinterpret_cast<const uint4*>(
                (tb ? g_Eout_h : g_Ein_h) + idx * 64)[c];
            uint32_t* dstp = (tb ? out_su[it] : in_su[it]) + k * 32 + c * 4;
            *reinterpret_cast<uint4*>(dstp) = u;
        }
    }
    __syncthreads();

    {
        const int it  = wid >> 1;
        const int dir = wid & 1;
        const uint32_t* qv = dir ? out_su[it] : in_su[it];
        const uint32_t* kv = dir ? in_su[it]  : out_su[it];
        float acc[KN];
        #pragma unroll
        for (int k = 0; k < KN; k++) acc[k] = 0.f;
        #pragma unroll
        for (int half = 0; half < 2; half++) {
            int i = lane + half * 32;
            float2 qp = bf2f(qv[i >> 1]);
            float qq = (i & 1) ? qp.y : qp.x;
            const uint32_t* kp = kv + i * 5;
            #pragma unroll
            for (int u = 0; u < 5; u++) {
                float2 f = bf2f(kp[u]);
                acc[2 * u]     += qq * f.x;
                acc[2 * u + 1] += qq * f.y;
            }
        }
        #pragma unroll
        for (int o = 16; o; o >>= 1)
            #pragma unroll
            for (int k = 0; k < KN; k++)
                acc[k] += __shfl_xor_sync(0xffffffffu, acc[k], o);
        if (lane < KN)
            (dir ? wi_s : wo_s)[it][lane] = expf(acc[lane] * 0.125f);
    }
    __syncthreads();

    if (t < 128) {
        const int it = t >> 5;
        const int dp = t & 31;
        float so = 0.f, si = 0.f;
        #pragma unroll
        for (int k = 0; k < KN; k++) { so += wo_s[it][k]; si += wi_s[it][k]; }
        float ro0 = 0.f, ro1 = 0.f, ri0 = 0.f, ri1 = 0.f;
        #pragma unroll
        for (int k = 0; k < KN; k++) {
            float2 fo = bf2f(out_su[it][k * 32 + dp]);
            float2 fi = bf2f(in_su [it][k * 32 + dp]);
            ro0 += wo_s[it][k] * fo.x;  ro1 += wo_s[it][k] * fo.y;
            ri0 += wi_s[it][k] * fi.x;  ri1 += wi_s[it][k] * fi.y;
        }
        float iso = 1.f / so, isi = 1.f / si;
        __nv_bfloat162 po = __floats2bfloat162_rn(ro0 * iso, ro1 * iso);
        __nv_bfloat162 pi = __floats2bfloat162_rn(ri0 * isi, ri1 * isi);
        reinterpret_cast<uint32_t*>(g_rout_h)[(nb + it) * 32 + dp] =
            *reinterpret_cast<uint32_t*>(&po);
        reinterpret_cast<uint32_t*>(g_rin_h)[(nb + it) * 32 + dp] =
            *reinterpret_cast<uint32_t*>(&pi);
    }
}

// ---------------- main kernel: dots folded into MMA (ones column) --------
#define SM_X   0
#define SM_W   (MROWS * PITCH_F)             // 17408
#define SM_AUX (SM_W + 128 * PITCH_F)        // 52224

struct Aux {
    float targ[256];
    float b1v[128];
    float w2v[128];
    float part[4][MROWS];
    float dots[MROWS];
    int   idxm[MROWS];
};
#define SMEM_TOTAL (SM_AUX + (int)sizeof(Aux))

__global__ __launch_bounds__(TBM, CTAS_SM)
void main_kernel(const int*   __restrict__ history,
                 const int*   __restrict__ target,
                 const float* __restrict__ b1,
                 const float* __restrict__ W2,
                 float*       __restrict__ out) {
    extern __shared__ char sm[];
    Aux* s = reinterpret_cast<Aux*>(sm + SM_AUX);
    const uint32_t sbase = smem_u32(sm);

    const int t    = threadIdx.x;
    const int wid  = t >> 5;
    const int lane = t & 31;

    const int m     = t >> 1;
    const int hhalf = t & 1;
    const bool rowvalid = (m < HIST);

    {
        uint4 z = make_uint4(0, 0, 0, 0);
        for (int i = t; i < MROWS * PITCH_F / 16; i += TBM)
            reinterpret_cast<uint4*>(sm + SM_X)[i] = z;
    }
    {
        const uint4* src = reinterpret_cast<const uint4*>(g_W8) + t * 16;
        char* dst = sm + SM_W + t * PITCH_F;
        #pragma unroll
        for (int g = 0; g < 16; g++)
            *reinterpret_cast<uint4*>(dst + g * 16) = src[g];
    }
    if (t < 128) { s->b1v[t] = b1[t]; s->w2v[t] = W2[t]; }
    __syncthreads();

    const int a_row0 = ((lane >> 3) & 1) * 8 + (lane & 7);
    const uint32_t a_addr0 = sbase + SM_X + a_row0 * PITCH_F + (lane >> 4) * 16;
    const int b_row = wid * 32 + (lane >> 4) * 8 + (lane & 7);
    const uint32_t b_addr0 = sbase + SM_W + b_row * PITCH_F + ((lane >> 3) & 1) * 16;

    // ones-column B fragment (e4m3 1.0 = 0x38), n-offset 0 -> lanes 0..3
    const uint32_t ones_b = (lane < 4) ? 0x38383838u : 0u;

    for (int p = blockIdx.x; p < BATCH; p += gridDim.x) {
        const int tg = target[p];

        // ---- phase 0: targ vector + history idx ----
        if (t < 32) {
            const uint4* src;
            int dstoff;
            if (t < 16)      { src = reinterpret_cast<const uint4*>(g_Etarg_h + tg * 128) + t;       dstoff = t * 8; }
            else if (t < 24) { src = reinterpret_cast<const uint4*>(g_rout_h  + tg * 64) + (t - 16); dstoff = 128 + (t - 16) * 8; }
            else             { src = reinterpret_cast<const uint4*>(g_rin_h   + tg * 64) + (t - 24); dstoff = 192 + (t - 24) * 8; }
            uint4 u = *src;
            const __nv_bfloat162* bp = reinterpret_cast<const __nv_bfloat162*>(&u);
            #pragma unroll
            for (int i = 0; i < 4; i++) {
                float2 f = __bfloat1622float2(bp[i]);
                s->targ[dstoff + 2 * i]     = f.x;
                s->targ[dstoff + 2 * i + 1] = f.y;
            }
        }
        int idx = 0;
        if (hhalf == 0 && rowvalid) idx = history[p * HIST + m];
        idx = __shfl_sync(0xffffffffu, idx, lane & ~1);
        if (hhalf == 0 && rowvalid) s->idxm[m] = idx;
        __syncthreads();

        // ---- phase 1: gather bf16, x = hist*targ -> fp8 smem (no dots) ----
        if (rowvalid) {
            const float* tgp = &s->targ[hhalf * 128];
            char* dst = sm + SM_X + m * PITCH_F + hhalf * 128;
            if (hhalf == 0) {
                const uint4* src = reinterpret_cast<const uint4*>(g_Ehist_h + idx * 128);
                #pragma unroll
                for (int g = 0; g < 8; g++)
                    mul16_store(src[2 * g], src[2 * g + 1], tgp + 16 * g,
                                dst + 16 * g);
            } else {
                const uint4* s0 = reinterpret_cast<const uint4*>(g_rin_h  + idx * 64);
                const uint4* s1 = reinterpret_cast<const uint4*>(g_rout_h + idx * 64);
                #pragma unroll
                for (int g = 0; g < 4; g++)
                    mul16_store(s0[2 * g], s0[2 * g + 1], tgp + 16 * g,
                                dst + 16 * g);
                #pragma unroll
                for (int g = 0; g < 4; g++)
                    mul16_store(s1[2 * g], s1[2 * g + 1], tgp + 64 + 16 * g,
                                dst + 64 + 16 * g);
            }
        }
        __syncthreads();

        // ---- phase 2: warp MMA 64x32 fp8 tile + dots column ----
        float d[4][4][4];
        #pragma unroll
        for (int mf = 0; mf < 4; mf++)
            #pragma unroll
            for (int g = 0; g < 4; g++)
                #pragma unroll
                for (int i = 0; i < 4; i++) d[mf][g][i] = 0.f;
        float d_dot[4] = {0.f, 0.f, 0.f, 0.f};

        #pragma unroll
        for (int ks = 0; ks < 8; ks++) {
            const uint32_t koff = ks * 32;
            uint32_t b0[4], b1r[4];
            ldmatrix_x4(b0[0], b0[1], b0[2], b0[3], b_addr0 + koff);
            ldmatrix_x4(b1r[0], b1r[1], b1r[2], b1r[3],
                        b_addr0 + 16 * PITCH_F + koff);
            #pragma unroll
            for (int mf = 0; mf < 4; mf++) {
                uint32_t a[4];
                ldmatrix_x4(a[0], a[1], a[2], a[3],
                            a_addr0 + mf * 16 * PITCH_F + koff);
                mma_fp8(d[mf][0][0], d[mf][0][1], d[mf][0][2], d[mf][0][3],
                        a[0], a[1], a[2], a[3], b0[0], b0[1]);
                mma_fp8(d[mf][1][0], d[mf][1][1], d[mf][1][2], d[mf][1][3],
                        a[0], a[1], a[2], a[3], b0[2], b0[3]);
                mma_fp8(d[mf][2][0], d[mf][2][1], d[mf][2][2], d[mf][2][3],
                        a[0], a[1], a[2], a[3], b1r[0], b1r[1]);
                mma_fp8(d[mf][3][0], d[mf][3][1], d[mf][3][2], d[mf][3][3],
                        a[0], a[1], a[2], a[3], b1r[2], b1r[3]);
                if (mf == wid)   // warp w computes dots for rows wid*16..+16
                    mma_fp8(d_dot[0], d_dot[1], d_dot[2], d_dot[3],
                            a[0], a[1], a[2], a[3], ones_b, ones_b);
            }
        }

        // ---- phase 3: epilogue relu(D*2^-20 + b1) * w2, reduce cols ----
        {
            float acc[4][2];
            #pragma unroll
            for (int mf = 0; mf < 4; mf++) { acc[mf][0] = 0.f; acc[mf][1] = 0.f; }
            #pragma unroll
            for (int g = 0; g < 4; g++) {
                const int c0 = wid * 32 + g * 8 + 2 * (lane & 3);
                const float bb0 = s->b1v[c0], bb1 = s->b1v[c0 + 1];
                const float ww0 = s->w2v[c0], ww1 = s->w2v[c0 + 1];
                #pragma unroll
                for (int mf = 0; mf < 4; mf++) {
                    acc[mf][0] += fmaxf(fmaf(d[mf][g][0], INV_SCALE, bb0), 0.f) * ww0
                                + fmaxf(fmaf(d[mf][g][1], INV_SCALE, bb1), 0.f) * ww1;
                    acc[mf][1] += fmaxf(fmaf(d[mf][g][2], INV_SCALE, bb0), 0.f) * ww0
                                + fmaxf(fmaf(d[mf][g][3], INV_SCALE, bb1), 0.f) * ww1;
                }
            }
            #pragma unroll
            for (int mf = 0; mf < 4; mf++) {
                #pragma unroll
                for (int i = 0; i < 2; i++) {
                    acc[mf][i] += __shfl_xor_sync(0xffffffffu, acc[mf][i], 1);
                    acc[mf][i] += __shfl_xor_sync(0xffffffffu, acc[mf][i], 2);
                }
            }
            if ((lane & 3) == 0) {
                #pragma unroll
                for (int mf = 0; mf < 4; mf++) {
                    const int row = mf * 16 + (lane >> 2);
                    s->part[wid][row]     = acc[mf][0];
                    s->part[wid][row + 8] = acc[mf][1];
                }
                // dots for this warp's 16 rows (col 0 of ones-column MMA)
                const int drow = wid * 16 + (lane >> 2);
                s->dots[drow]     = d_dot[0] * INV_DOT;
                s->dots[drow + 8] = d_dot[2] * INV_DOT;
            }
        }
        __syncthreads();

        // ---- phase 4: masked exp weighting + prediction (warp 0) ----
        if (wid == 0) {
            float num = 0.f, den = 0.f;
            #pragma unroll
            for (int it = 0; it < 2; it++) {
                int hh = lane + it * 32;
                if (hh < HIST) {
                    float sc = (s->part[0][hh] + s->part[1][hh]) +
                               (s->part[2][hh] + s->part[3][hh]);
                    float e = expf(sc);
                    if (s->idxm[hh] == tg) e = 0.f;
                    num += e * s->dots[hh];
                    den += e;
                }
            }
            #pragma unroll
            for (int o = 16; o; o >>= 1) {
                num += __shfl_xor_sync(0xffffffffu, num, o);
                den += __shfl_xor_sync(0xffffffffu, den, o);
            }
            if (lane == 0) {
                float pred = num / sqrtf(den);     // BETA = 0.5
                out[p] = 1.f / (1.f + expf(-pred));
            }
        }
        __syncthreads();
    }
}

// ---------------- launch ----------------
extern "C" void kernel_launch(void* const* d_in, const int* in_sizes, int n_in,
                              void* d_out, int out_size) {
    const int*   history = (const int*)  d_in[0];
    const int*   target  = (const int*)  d_in[1];
    const int*   near_p  = (const int*)  d_in[2];
    const float* E_in    = (const float*)d_in[4];
    const float* E_out   = (const float*)d_in[5];
    const float* E_hist  = (const float*)d_in[6];
    const float* E_targ  = (const float*)d_in[7];
    const float* W1      = (const float*)d_in[8];
    const float* b1      = (const float*)d_in[9];
    const float* W2      = (const float*)d_in[10];
    float* out = (float*)d_out;

    conv1_kernel<<<400, 256>>>(E_in, E_out);
    prep2_kernel<<<PREP2_GRID, 256>>>(near_p, E_hist, E_targ, W1);

    cudaFuncSetAttribute(main_kernel,
                         cudaFuncAttributeMaxDynamicSharedMemorySize,
                         SMEM_TOTAL);
    main_kernel<<<GRIDM, TBM, SMEM_TOTAL>>>(history, target, b1, W2, out);
}

// round 13
// speedup vs baseline: 1.2166x; 1.2166x over previous
#include <cuda_runtime.h>
#include <cuda_fp16.h>
#include <cstdint>
#include <math.h>

#define ITEM_NUM 50000
#define BATCH    4096
#define HIST     50
#define KN       10

#define TBM      128               // main kernel threads (4 warps)
#define CTAS_SM  4
#define GRIDM    (148 * CTAS_SM)   // 592
#define MROWS    64                // M tile (1 batch element, 50 valid rows)

#define PITCH_F  272               // fp8 pitch (68 words = 4 mod 32 banks)

#define SCALE_X   4096.0f          // 2^12 (targ pre-scale)
#define SCALE_W   256.0f           // 2^8
#define INV_SCALE 9.5367431640625e-7f   // 2^-20
#define INV_DOT   2.44140625e-4f        // 2^-12

#define CONV_BLKS   500
#define REGION_BLKS (ITEM_NUM / 4)  // 12500
#define PREP2_GRID  (REGION_BLKS + CONV_BLKS)

// ---------------- device scratch (fp16 tables) ----------------
__device__ __half    g_Ein_h  [ITEM_NUM * 64];
__device__ __half    g_Eout_h [ITEM_NUM * 64];
__device__ __half    g_Ehist_h[ITEM_NUM * 128];
__device__ __half    g_Etarg_h[ITEM_NUM * 128];
__device__ __half    g_rin_h  [ITEM_NUM * 64];
__device__ __half    g_rout_h [ITEM_NUM * 64];
__device__ uint32_t  g_W8     [128 * 256 / 4];   // fp8-packed W1 * 2^8

// ---------------- PTX helpers ----------------
__device__ __forceinline__ uint32_t smem_u32(const void* p) {
    uint32_t a;
    asm("{ .reg .u64 t; cvta.to.shared.u64 t, %1; cvt.u32.u64 %0, t; }" : "=r"(a) : "l"(p));
    return a;
}

__device__ __forceinline__ void ldmatrix_x4(uint32_t& r0, uint32_t& r1,
                                            uint32_t& r2, uint32_t& r3,
                                            uint32_t addr) {
    asm volatile("ldmatrix.sync.aligned.m8n8.x4.shared.b16 {%0,%1,%2,%3}, [%4];"
                 : "=r"(r0), "=r"(r1), "=r"(r2), "=r"(r3) : "r"(addr));
}

__device__ __forceinline__ void mma_fp8(float& d0, float& d1, float& d2, float& d3,
                                        uint32_t a0, uint32_t a1, uint32_t a2, uint32_t a3,
                                        uint32_t b0, uint32_t b1) {
    asm volatile(
        "mma.sync.aligned.m16n8k32.row.col.f32.e4m3.e4m3.f32 "
        "{%0,%1,%2,%3}, {%4,%5,%6,%7}, {%8,%9}, {%0,%1,%2,%3};"
        : "+f"(d0), "+f"(d1), "+f"(d2), "+f"(d3)
        : "r"(a0), "r"(a1), "r"(a2), "r"(a3), "r"(b0), "r"(b1));
}

__device__ __forceinline__ uint32_t pack4_e4m3(float f0, float f1, float f2, float f3) {
    uint16_t lo, hi;
    asm("cvt.rn.satfinite.e4m3x2.f32 %0, %1, %2;" : "=h"(lo) : "f"(f1), "f"(f0));
    asm("cvt.rn.satfinite.e4m3x2.f32 %0, %1, %2;" : "=h"(hi) : "f"(f3), "f"(f2));
    return (uint32_t)lo | ((uint32_t)hi << 16);
}

// two f16x2 words -> 4 e4m3 bytes (element order preserved)
__device__ __forceinline__ uint32_t pack_e4m3_h2(uint32_t h2a, uint32_t h2b) {
    uint16_t lo, hi;
    asm("cvt.rn.satfinite.e4m3x2.f16x2 %0, %1;" : "=h"(lo) : "r"(h2a));
    asm("cvt.rn.satfinite.e4m3x2.f16x2 %0, %1;" : "=h"(hi) : "r"(h2b));
    return (uint32_t)lo | ((uint32_t)hi << 16);
}

__device__ __forceinline__ uint2 f4_to_h4(float4 a) {
    __half2 p0 = __floats2half2_rn(a.x, a.y);
    __half2 p1 = __floats2half2_rn(a.z, a.w);
    uint2 u;
    u.x = *reinterpret_cast<uint32_t*>(&p0);
    u.y = *reinterpret_cast<uint32_t*>(&p1);
    return u;
}

__device__ __forceinline__ float2 h2f(uint32_t w) {
    return __half22float2(*reinterpret_cast<__half2*>(&w));
}
__device__ __forceinline__ __half2 as_h2(uint32_t w) {
    return *reinterpret_cast<__half2*>(&w);
}
__device__ __forceinline__ uint32_t as_u32(__half2 h) {
    return *reinterpret_cast<uint32_t*>(&h);
}

// 16 half (two uint4) * 16 pre-scaled half targ -> fp8x16; half2 dot accum
__device__ __forceinline__ void mul16_h(uint4 u0, uint4 u1, const uint32_t* tg,
                                        __half2& acc, void* dst) {
    const uint32_t* h0 = reinterpret_cast<const uint32_t*>(&u0);
    const uint32_t* h1 = reinterpret_cast<const uint32_t*>(&u1);
    uint32_t xw[8];
    #pragma unroll
    for (int i = 0; i < 4; i++) {
        __half2 x = __hmul2(as_h2(h0[i]), as_h2(tg[i]));
        acc = __hadd2(acc, x);
        xw[i] = as_u32(x);
    }
    #pragma unroll
    for (int i = 0; i < 4; i++) {
        __half2 x = __hmul2(as_h2(h1[i]), as_h2(tg[4 + i]));
        acc = __hadd2(acc, x);
        xw[4 + i] = as_u32(x);
    }
    uint4 o;
    o.x = pack_e4m3_h2(xw[0], xw[1]);
    o.y = pack_e4m3_h2(xw[2], xw[3]);
    o.z = pack_e4m3_h2(xw[4], xw[5]);
    o.w = pack_e4m3_h2(xw[6], xw[7]);
    *reinterpret_cast<uint4*>(dst) = o;
}

// ---------------- kernel 1: convert E_in / E_out -> fp16 ------------------
__global__ __launch_bounds__(256)
void conv1_kernel(const float* __restrict__ E_in,
                  const float* __restrict__ E_out) {
    int i = blockIdx.x * 256 + threadIdx.x;
    int stride = gridDim.x * 256;
    const float4* in4  = reinterpret_cast<const float4*>(E_in);
    const float4* out4 = reinterpret_cast<const float4*>(E_out);
    uint2* din  = reinterpret_cast<uint2*>(g_Ein_h);
    uint2* dout = reinterpret_cast<uint2*>(g_Eout_h);
    for (int v = i; v < ITEM_NUM * 64 / 4; v += stride) {
        din [v] = f4_to_h4(in4 [v]);
        dout[v] = f4_to_h4(out4[v]);
    }
}

// ---------------- kernel 2: conversions FIRST, region attention after ----
__global__ __launch_bounds__(256)
void prep2_kernel(const int*   __restrict__ near_pois,
                  const float* __restrict__ E_hist,
                  const float* __restrict__ E_targ,
                  const float* __restrict__ W1) {
    const int t = threadIdx.x;

    if (blockIdx.x < CONV_BLKS) {
        int i = blockIdx.x * 256 + t;
        int stride = CONV_BLKS * 256;
        const float4* hi4 = reinterpret_cast<const float4*>(E_hist);
        const float4* tg4 = reinterpret_cast<const float4*>(E_targ);
        const float4* w4  = reinterpret_cast<const float4*>(W1);
        uint2* dhi = reinterpret_cast<uint2*>(g_Ehist_h);
        uint2* dtg = reinterpret_cast<uint2*>(g_Etarg_h);
        for (int v = i; v < ITEM_NUM * 128 / 4; v += stride) {
            dhi[v] = f4_to_h4(hi4[v]);
            dtg[v] = f4_to_h4(tg4[v]);
        }
        for (int v = i; v < 128 * 256 / 4; v += stride) {
            float4 a = w4[v];
            g_W8[v] = pack4_e4m3(a.x * SCALE_W, a.y * SCALE_W,
                                 a.z * SCALE_W, a.w * SCALE_W);
        }
        return;
    }

    // ---- region part: fp16-resident smem ----
    __shared__ uint32_t in_su [4][320];
    __shared__ uint32_t out_su[4][320];
    __shared__ float    wo_s  [4][10];
    __shared__ float    wi_s  [4][10];
    __shared__ int      idx_s [4][10];

    const int wid  = t >> 5;
    const int lane = t & 31;
    const int nb   = (blockIdx.x - CONV_BLKS) * 4;

    if (t < 40) idx_s[t / 10][t % 10] = near_pois[(nb + t / 10) * KN + t % 10];
    __syncthreads();

    #pragma unroll
    for (int w = 0; w < 3; w++) {
        int v = t + w * 256;
        if (v < 640) {
            int it = v / 160;
            int r0 = v - it * 160;
            int tb = (r0 >= 80) ? 1 : 0;
            int rr = r0 - tb * 80;
            int k = rr >> 3, c = rr & 7;
            int idx = idx_s[it][k];
            uint4 u = reinterpret_cast<const uint4*>(
                (tb ? g_Eout_h : g_Ein_h) + idx * 64)[c];
            uint32_t* dstp = (tb ? out_su[it] : in_su[it]) + k * 32 + c * 4;
            *reinterpret_cast<uint4*>(dstp) = u;
        }
    }
    __syncthreads();

    {
        const int it  = wid >> 1;
        const int dir = wid & 1;
        const uint32_t* qv = dir ? out_su[it] : in_su[it];
        const uint32_t* kv = dir ? in_su[it]  : out_su[it];
        float acc[KN];
        #pragma unroll
        for (int k = 0; k < KN; k++) acc[k] = 0.f;
        #pragma unroll
        for (int half = 0; half < 2; half++) {
            int i = lane + half * 32;
            float2 qp = h2f(qv[i >> 1]);
            float qq = (i & 1) ? qp.y : qp.x;
            const uint32_t* kp = kv + i * 5;
            #pragma unroll
            for (int u = 0; u < 5; u++) {
                float2 f = h2f(kp[u]);
                acc[2 * u]     += qq * f.x;
                acc[2 * u + 1] += qq * f.y;
            }
        }
        #pragma unroll
        for (int o = 16; o; o >>= 1)
            #pragma unroll
            for (int k = 0; k < KN; k++)
                acc[k] += __shfl_xor_sync(0xffffffffu, acc[k], o);
        if (lane < KN)
            (dir ? wi_s : wo_s)[it][lane] = expf(acc[lane] * 0.125f);
    }
    __syncthreads();

    if (t < 128) {
        const int it = t >> 5;
        const int dp = t & 31;
        float so = 0.f, si = 0.f;
        #pragma unroll
        for (int k = 0; k < KN; k++) { so += wo_s[it][k]; si += wi_s[it][k]; }
        float ro0 = 0.f, ro1 = 0.f, ri0 = 0.f, ri1 = 0.f;
        #pragma unroll
        for (int k = 0; k < KN; k++) {
            float2 fo = h2f(out_su[it][k * 32 + dp]);
            float2 fi = h2f(in_su [it][k * 32 + dp]);
            ro0 += wo_s[it][k] * fo.x;  ro1 += wo_s[it][k] * fo.y;
            ri0 += wi_s[it][k] * fi.x;  ri1 += wi_s[it][k] * fi.y;
        }
        float iso = 1.f / so, isi = 1.f / si;
        __half2 po = __floats2half2_rn(ro0 * iso, ro1 * iso);
        __half2 pi = __floats2half2_rn(ri0 * isi, ri1 * isi);
        reinterpret_cast<uint32_t*>(g_rout_h)[(nb + it) * 32 + dp] = as_u32(po);
        reinterpret_cast<uint32_t*>(g_rin_h)[(nb + it) * 32 + dp]  = as_u32(pi);
    }
}

// ---------------- main kernel: fp16 gather chain, R11 structure ----------
#define SM_X   0
#define SM_W   (MROWS * PITCH_F)             // 17408
#define SM_AUX (SM_W + 128 * PITCH_F)        // 52224

struct Aux {
    uint32_t targ2[128];   // 256 halves, pre-scaled by 2^12
    float b1v[128];
    float w2v[128];
    float part[4][MROWS];
    float dots[MROWS];
    int   idxm[MROWS];
};
#define SMEM_TOTAL (SM_AUX + (int)sizeof(Aux))

__global__ __launch_bounds__(TBM, CTAS_SM)
void main_kernel(const int*   __restrict__ history,
                 const int*   __restrict__ target,
                 const float* __restrict__ b1,
                 const float* __restrict__ W2,
                 float*       __restrict__ out) {
    extern __shared__ char sm[];
    Aux* s = reinterpret_cast<Aux*>(sm + SM_AUX);
    const uint32_t sbase = smem_u32(sm);

    const int t    = threadIdx.x;
    const int wid  = t >> 5;
    const int lane = t & 31;

    const int m     = t >> 1;
    const int hhalf = t & 1;
    const bool rowvalid = (m < HIST);

    {
        uint4 z = make_uint4(0, 0, 0, 0);
        for (int i = t; i < MROWS * PITCH_F / 16; i += TBM)
            reinterpret_cast<uint4*>(sm + SM_X)[i] = z;
    }
    {
        const uint4* src = reinterpret_cast<const uint4*>(g_W8) + t * 16;
        char* dst = sm + SM_W + t * PITCH_F;
        #pragma unroll
        for (int g = 0; g < 16; g++)
            *reinterpret_cast<uint4*>(dst + g * 16) = src[g];
    }
    if (t < 128) { s->b1v[t] = b1[t]; s->w2v[t] = W2[t]; }
    __syncthreads();

    const int a_row0 = ((lane >> 3) & 1) * 8 + (lane & 7);
    const uint32_t a_addr0 = sbase + SM_X + a_row0 * PITCH_F + (lane >> 4) * 16;
    const int b_row = wid * 32 + (lane >> 4) * 8 + (lane & 7);
    const uint32_t b_addr0 = sbase + SM_W + b_row * PITCH_F + ((lane >> 3) & 1) * 16;

    const __half2 hscale = __floats2half2_rn(SCALE_X, SCALE_X);

    for (int p = blockIdx.x; p < BATCH; p += gridDim.x) {
        const int tg = target[p];

        // ---- phase 0: targ (pre-scaled fp16) + history idx ----
        if (t < 32) {
            const uint4* src;
            int woff;   // word offset into targ2
            if (t < 16)      { src = reinterpret_cast<const uint4*>(g_Etarg_h + tg * 128) + t;       woff = t * 4; }
            else if (t < 24) { src = reinterpret_cast<const uint4*>(g_rout_h  + tg * 64) + (t - 16); woff = 64 + (t - 16) * 4; }
            else             { src = reinterpret_cast<const uint4*>(g_rin_h   + tg * 64) + (t - 24); woff = 96 + (t - 24) * 4; }
            uint4 u = *src;
            const uint32_t* up = reinterpret_cast<const uint32_t*>(&u);
            #pragma unroll
            for (int i = 0; i < 4; i++)
                s->targ2[woff + i] = as_u32(__hmul2(as_h2(up[i]), hscale));
        }
        int idx = 0;
        if (hhalf == 0 && rowvalid) idx = history[p * HIST + m];
        idx = __shfl_sync(0xffffffffu, idx, lane & ~1);
        if (hhalf == 0 && rowvalid) s->idxm[m] = idx;
        __syncthreads();

        // ---- phase 1: gather fp16, x = hist*targ' -> fp8 smem; h2 dots ----
        __half2 acc = __floats2half2_rn(0.f, 0.f);
        if (rowvalid) {
            const uint32_t* tgp = &s->targ2[hhalf * 64];
            char* dst = sm + SM_X + m * PITCH_F + hhalf * 128;
            if (hhalf == 0) {
                const uint4* src = reinterpret_cast<const uint4*>(g_Ehist_h + idx * 128);
                #pragma unroll
                for (int g = 0; g < 8; g++)
                    mul16_h(src[2 * g], src[2 * g + 1], tgp + 8 * g, acc,
                            dst + 16 * g);
            } else {
                const uint4* s0 = reinterpret_cast<const uint4*>(g_rin_h  + idx * 64);
                const uint4* s1 = reinterpret_cast<const uint4*>(g_rout_h + idx * 64);
                #pragma unroll
                for (int g = 0; g < 4; g++)
                    mul16_h(s0[2 * g], s0[2 * g + 1], tgp + 8 * g, acc,
                            dst + 16 * g);
                #pragma unroll
                for (int g = 0; g < 4; g++)
                    mul16_h(s1[2 * g], s1[2 * g + 1], tgp + 32 + 8 * g, acc,
                            dst + 64 + 16 * g);
            }
        }
        float2 df = __half22float2(acc);
        float dot = (df.x + df.y) * INV_DOT;
        dot += __shfl_xor_sync(0xffffffffu, dot, 1);
        if (hhalf == 0 && rowvalid) s->dots[m] = dot;
        __syncthreads();

        // ---- phase 2: warp MMA 64x32 fp8 tile ----
        float d[4][4][4];
        #pragma unroll
        for (int mf = 0; mf < 4; mf++)
            #pragma unroll
            for (int g = 0; g < 4; g++)
                #pragma unroll
                for (int i = 0; i < 4; i++) d[mf][g][i] = 0.f;

        #pragma unroll
        for (int ks = 0; ks < 8; ks++) {
            const uint32_t koff = ks * 32;
            uint32_t b0[4], b1r[4];
            ldmatrix_x4(b0[0], b0[1], b0[2], b0[3], b_addr0 + koff);
            ldmatrix_x4(b1r[0], b1r[1], b1r[2], b1r[3],
                        b_addr0 + 16 * PITCH_F + koff);
            #pragma unroll
            for (int mf = 0; mf < 4; mf++) {
                uint32_t a[4];
                ldmatrix_x4(a[0], a[1], a[2], a[3],
                            a_addr0 + mf * 16 * PITCH_F + koff);
                mma_fp8(d[mf][0][0], d[mf][0][1], d[mf][0][2], d[mf][0][3],
                        a[0], a[1], a[2], a[3], b0[0], b0[1]);
                mma_fp8(d[mf][1][0], d[mf][1][1], d[mf][1][2], d[mf][1][3],
                        a[0], a[1], a[2], a[3], b0[2], b0[3]);
                mma_fp8(d[mf][2][0], d[mf][2][1], d[mf][2][2], d[mf][2][3],
                        a[0], a[1], a[2], a[3], b1r[0], b1r[1]);
                mma_fp8(d[mf][3][0], d[mf][3][1], d[mf][3][2], d[mf][3][3],
                        a[0], a[1], a[2], a[3], b1r[2], b1r[3]);
            }
        }

        // ---- phase 3: epilogue relu(D*2^-20 + b1) * w2, reduce cols ----
        {
            float acc2[4][2];
            #pragma unroll
            for (int mf = 0; mf < 4; mf++) { acc2[mf][0] = 0.f; acc2[mf][1] = 0.f; }
            #pragma unroll
            for (int g = 0; g < 4; g++) {
                const int c0 = wid * 32 + g * 8 + 2 * (lane & 3);
                const float bb0 = s->b1v[c0], bb1 = s->b1v[c0 + 1];
                const float ww0 = s->w2v[c0], ww1 = s->w2v[c0 + 1];
                #pragma unroll
                for (int mf = 0; mf < 4; mf++) {
                    acc2[mf][0] += fmaxf(fmaf(d[mf][g][0], INV_SCALE, bb0), 0.f) * ww0
                                 + fmaxf(fmaf(d[mf][g][1], INV_SCALE, bb1), 0.f) * ww1;
                    acc2[mf][1] += fmaxf(fmaf(d[mf][g][2], INV_SCALE, bb0), 0.f) * ww0
                                 + fmaxf(fmaf(d[mf][g][3], INV_SCALE, bb1), 0.f) * ww1;
                }
            }
            #pragma unroll
            for (int mf = 0; mf < 4; mf++) {
                #pragma unroll
                for (int i = 0; i < 2; i++) {
                    acc2[mf][i] += __shfl_xor_sync(0xffffffffu, acc2[mf][i], 1);
                    acc2[mf][i] += __shfl_xor_sync(0xffffffffu, acc2[mf][i], 2);
                }
            }
            if ((lane & 3) == 0) {
                #pragma unroll
                for (int mf = 0; mf < 4; mf++) {
                    const int row = mf * 16 + (lane >> 2);
                    s->part[wid][row]     = acc2[mf][0];
                    s->part[wid][row + 8] = acc2[mf][1];
                }
            }
        }
        __syncthreads();

        // ---- phase 4: masked exp weighting + prediction (warp 0) ----
        if (wid == 0) {
            float num = 0.f, den = 0.f;
            #pragma unroll
            for (int it = 0; it < 2; it++) {
                int hh = lane + it * 32;
                if (hh < HIST) {
                    float sc = (s->part[0][hh] + s->part[1][hh]) +
                               (s->part[2][hh] + s->part[3][hh]);
                    float e = expf(sc);
                    if (s->idxm[hh] == tg) e = 0.f;
                    num += e * s->dots[hh];
                    den += e;
                }
            }
            #pragma unroll
            for (int o = 16; o; o >>= 1) {
                num += __shfl_xor_sync(0xffffffffu, num, o);
                den += __shfl_xor_sync(0xffffffffu, den, o);
            }
            if (lane == 0) {
                float pred = num / sqrtf(den);     // BETA = 0.5
                out[p] = 1.f / (1.f + expf(-pred));
            }
        }
        __syncthreads();
    }
}

// ---------------- launch ----------------
extern "C" void kernel_launch(void* const* d_in, const int* in_sizes, int n_in,
                              void* d_out, int out_size) {
    const int*   history = (const int*)  d_in[0];
    const int*   target  = (const int*)  d_in[1];
    const int*   near_p  = (const int*)  d_in[2];
    const float* E_in    = (const float*)d_in[4];
    const float* E_out   = (const float*)d_in[5];
    const float* E_hist  = (const float*)d_in[6];
    const float* E_targ  = (const float*)d_in[7];
    const float* W1      = (const float*)d_in[8];
    const float* b1      = (const float*)d_in[9];
    const float* W2      = (const float*)d_in[10];
    float* out = (float*)d_out;

    conv1_kernel<<<400, 256>>>(E_in, E_out);
    prep2_kernel<<<PREP2_GRID, 256>>>(near_p, E_hist, E_targ, W1);

    cudaFuncSetAttribute(main_kernel,
                         cudaFuncAttributeMaxDynamicSharedMemorySize,
                         SMEM_TOTAL);
    main_kernel<<<GRIDM, TBM, SMEM_TOTAL>>>(history, target, b1, W2, out);
}

// round 14
// speedup vs baseline: 1.2540x; 1.0308x over previous
#include <cuda_runtime.h>
#include <cuda_fp16.h>
#include <cstdint>
#include <math.h>

#define ITEM_NUM 50000
#define BATCH    4096
#define HIST     50
#define KN       10

#define TBM      128               // main kernel threads (4 warps)
#define CTAS_SM  4
#define GRIDM    (148 * CTAS_SM)   // 592
#define MROWS    64                // M tile (1 batch element, 50 valid rows)

#define PITCH_F  272               // fp8 pitch (68 words = 4 mod 32 banks)

#define SCALE_X   4096.0f          // 2^12 (targ pre-scale)
#define SCALE_W   256.0f           // 2^8
#define INV_SCALE 9.5367431640625e-7f   // 2^-20
#define INV_DOT   2.44140625e-4f        // 2^-12

#define NIT      8                  // region items per block
#define CONV_BLKS   500
#define REGION_BLKS (ITEM_NUM / NIT)  // 6250
#define PREP2_GRID  (REGION_BLKS + CONV_BLKS)

// ---------------- device scratch (fp16 tables) ----------------
__device__ __half    g_Ein_h  [ITEM_NUM * 64];
__device__ __half    g_Eout_h [ITEM_NUM * 64];
__device__ __half    g_Ehist_h[ITEM_NUM * 128];
__device__ __half    g_Etarg_h[ITEM_NUM * 128];
__device__ __half    g_rin_h  [ITEM_NUM * 64];
__device__ __half    g_rout_h [ITEM_NUM * 64];
__device__ uint32_t  g_W8     [128 * 256 / 4];   // fp8-packed W1 * 2^8

// ---------------- PTX helpers ----------------
__device__ __forceinline__ uint32_t smem_u32(const void* p) {
    uint32_t a;
    asm("{ .reg .u64 t; cvta.to.shared.u64 t, %1; cvt.u32.u64 %0, t; }" : "=r"(a) : "l"(p));
    return a;
}

__device__ __forceinline__ void ldmatrix_x4(uint32_t& r0, uint32_t& r1,
                                            uint32_t& r2, uint32_t& r3,
                                            uint32_t addr) {
    asm volatile("ldmatrix.sync.aligned.m8n8.x4.shared.b16 {%0,%1,%2,%3}, [%4];"
                 : "=r"(r0), "=r"(r1), "=r"(r2), "=r"(r3) : "r"(addr));
}

__device__ __forceinline__ void mma_fp8(float& d0, float& d1, float& d2, float& d3,
                                        uint32_t a0, uint32_t a1, uint32_t a2, uint32_t a3,
                                        uint32_t b0, uint32_t b1) {
    asm volatile(
        "mma.sync.aligned.m16n8k32.row.col.f32.e4m3.e4m3.f32 "
        "{%0,%1,%2,%3}, {%4,%5,%6,%7}, {%8,%9}, {%0,%1,%2,%3};"
        : "+f"(d0), "+f"(d1), "+f"(d2), "+f"(d3)
        : "r"(a0), "r"(a1), "r"(a2), "r"(a3), "r"(b0), "r"(b1));
}

__device__ __forceinline__ uint32_t pack4_e4m3(float f0, float f1, float f2, float f3) {
    uint16_t lo, hi;
    asm("cvt.rn.satfinite.e4m3x2.f32 %0, %1, %2;" : "=h"(lo) : "f"(f1), "f"(f0));
    asm("cvt.rn.satfinite.e4m3x2.f32 %0, %1, %2;" : "=h"(hi) : "f"(f3), "f"(f2));
    return (uint32_t)lo | ((uint32_t)hi << 16);
}

__device__ __forceinline__ uint32_t pack_e4m3_h2(uint32_t h2a, uint32_t h2b) {
    uint16_t lo, hi;
    asm("cvt.rn.satfinite.e4m3x2.f16x2 %0, %1;" : "=h"(lo) : "r"(h2a));
    asm("cvt.rn.satfinite.e4m3x2.f16x2 %0, %1;" : "=h"(hi) : "r"(h2b));
    return (uint32_t)lo | ((uint32_t)hi << 16);
}

__device__ __forceinline__ uint2 f4_to_h4(float4 a) {
    __half2 p0 = __floats2half2_rn(a.x, a.y);
    __half2 p1 = __floats2half2_rn(a.z, a.w);
    uint2 u;
    u.x = *reinterpret_cast<uint32_t*>(&p0);
    u.y = *reinterpret_cast<uint32_t*>(&p1);
    return u;
}

__device__ __forceinline__ float2 h2f(uint32_t w) {
    return __half22float2(*reinterpret_cast<__half2*>(&w));
}
__device__ __forceinline__ __half2 as_h2(uint32_t w) {
    return *reinterpret_cast<__half2*>(&w);
}
__device__ __forceinline__ uint32_t as_u32(__half2 h) {
    return *reinterpret_cast<uint32_t*>(&h);
}

__device__ __forceinline__ void mul16_h(uint4 u0, uint4 u1, const uint32_t* tg,
                                        __half2& acc, void* dst) {
    const uint32_t* h0 = reinterpret_cast<const uint32_t*>(&u0);
    const uint32_t* h1 = reinterpret_cast<const uint32_t*>(&u1);
    uint32_t xw[8];
    #pragma unroll
    for (int i = 0; i < 4; i++) {
        __half2 x = __hmul2(as_h2(h0[i]), as_h2(tg[i]));
        acc = __hadd2(acc, x);
        xw[i] = as_u32(x);
    }
    #pragma unroll
    for (int i = 0; i < 4; i++) {
        __half2 x = __hmul2(as_h2(h1[i]), as_h2(tg[4 + i]));
        acc = __hadd2(acc, x);
        xw[4 + i] = as_u32(x);
    }
    uint4 o;
    o.x = pack_e4m3_h2(xw[0], xw[1]);
    o.y = pack_e4m3_h2(xw[2], xw[3]);
    o.z = pack_e4m3_h2(xw[4], xw[5]);
    o.w = pack_e4m3_h2(xw[6], xw[7]);
    *reinterpret_cast<uint4*>(dst) = o;
}

// ---------------- kernel 1: convert E_in / E_out -> fp16 ------------------
__global__ __launch_bounds__(256)
void conv1_kernel(const float* __restrict__ E_in,
                  const float* __restrict__ E_out) {
    int i = blockIdx.x * 256 + threadIdx.x;
    int stride = gridDim.x * 256;
    const float4* in4  = reinterpret_cast<const float4*>(E_in);
    const float4* out4 = reinterpret_cast<const float4*>(E_out);
    uint2* din  = reinterpret_cast<uint2*>(g_Ein_h);
    uint2* dout = reinterpret_cast<uint2*>(g_Eout_h);
    for (int v = i; v < ITEM_NUM * 64 / 4; v += stride) {
        din [v] = f4_to_h4(in4 [v]);
        dout[v] = f4_to_h4(out4[v]);
    }
}

// ---------------- kernel 2: conversions FIRST, region attention after ----
// blocks [0, 500): convert E_hist/E_targ -> fp16, W1 -> fp8
// blocks [500, 6750): region self-attention, 8 items/block
__global__ __launch_bounds__(256)
void prep2_kernel(const int*   __restrict__ near_pois,
                  const float* __restrict__ E_hist,
                  const float* __restrict__ E_targ,
                  const float* __restrict__ W1) {
    const int t = threadIdx.x;

    if (blockIdx.x < CONV_BLKS) {
        int i = blockIdx.x * 256 + t;
        int stride = CONV_BLKS * 256;
        const float4* hi4 = reinterpret_cast<const float4*>(E_hist);
        const float4* tg4 = reinterpret_cast<const float4*>(E_targ);
        const float4* w4  = reinterpret_cast<const float4*>(W1);
        uint2* dhi = reinterpret_cast<uint2*>(g_Ehist_h);
        uint2* dtg = reinterpret_cast<uint2*>(g_Etarg_h);
        for (int v = i; v < ITEM_NUM * 128 / 4; v += stride) {
            dhi[v] = f4_to_h4(hi4[v]);
            dtg[v] = f4_to_h4(tg4[v]);
        }
        for (int v = i; v < 128 * 256 / 4; v += stride) {
            float4 a = w4[v];
            g_W8[v] = pack4_e4m3(a.x * SCALE_W, a.y * SCALE_W,
                                 a.z * SCALE_W, a.w * SCALE_W);
        }
        return;
    }

    // ---- region part: 8 items/block, fp16-resident smem ----
    __shared__ uint32_t in_su [NIT][320];
    __shared__ uint32_t out_su[NIT][320];
    __shared__ float    wo_s  [NIT][10];
    __shared__ float    wi_s  [NIT][10];
    __shared__ int      idx_s [NIT][10];

    const int wid  = t >> 5;
    const int lane = t & 31;
    const int nb   = (blockIdx.x - CONV_BLKS) * NIT;

    if (t < NIT * 10) idx_s[t / 10][t % 10] = near_pois[(nb + t / 10) * KN + t % 10];
    __syncthreads();

    // gather: 1280 uint4 (8 items x 2 tables x 10 rows x 8 chunks), 5/thread
    #pragma unroll
    for (int w = 0; w < 5; w++) {
        int v = t + w * 256;
        int it = v / 160;
        int r0 = v - it * 160;
        int tb = (r0 >= 80) ? 1 : 0;
        int rr = r0 - tb * 80;
        int k = rr >> 3, c = rr & 7;
        int idx = idx_s[it][k];
        uint4 u = reinterpret_cast<const uint4*>(
            (tb ? g_Eout_h : g_Ein_h) + idx * 64)[c];
        uint32_t* dstp = (tb ? out_su[it] : in_su[it]) + k * 32 + c * 4;
        *reinterpret_cast<uint4*>(dstp) = u;
    }
    __syncthreads();

    // scores: 16 tasks (item, dir), 8 warps -> 2 tasks each
    #pragma unroll
    for (int task = wid; task < 2 * NIT; task += 8) {
        const int it  = task >> 1;
        const int dir = task & 1;
        const uint32_t* qv = dir ? out_su[it] : in_su[it];
        const uint32_t* kv = dir ? in_su[it]  : out_su[it];
        float acc[KN];
        #pragma unroll
        for (int k = 0; k < KN; k++) acc[k] = 0.f;
        #pragma unroll
        for (int half = 0; half < 2; half++) {
            int i = lane + half * 32;
            float2 qp = h2f(qv[i >> 1]);
            float qq = (i & 1) ? qp.y : qp.x;
            const uint32_t* kp = kv + i * 5;
            #pragma unroll
            for (int u = 0; u < 5; u++) {
                float2 f = h2f(kp[u]);
                acc[2 * u]     += qq * f.x;
                acc[2 * u + 1] += qq * f.y;
            }
        }
        #pragma unroll
        for (int o = 16; o; o >>= 1)
            #pragma unroll
            for (int k = 0; k < KN; k++)
                acc[k] += __shfl_xor_sync(0xffffffffu, acc[k], o);
        if (lane < KN)
            (dir ? wi_s : wo_s)[it][lane] = expf(acc[lane] * 0.125f);
    }
    __syncthreads();

    // weighted aggregation: 8 items x 32 dim-pairs = 256 threads exactly
    {
        const int it = t >> 5;
        const int dp = t & 31;
        float so = 0.f, si = 0.f;
        #pragma unroll
        for (int k = 0; k < KN; k++) { so += wo_s[it][k]; si += wi_s[it][k]; }
        float ro0 = 0.f, ro1 = 0.f, ri0 = 0.f, ri1 = 0.f;
        #pragma unroll
        for (int k = 0; k < KN; k++) {
            float2 fo = h2f(out_su[it][k * 32 + dp]);
            float2 fi = h2f(in_su [it][k * 32 + dp]);
            ro0 += wo_s[it][k] * fo.x;  ro1 += wo_s[it][k] * fo.y;
            ri0 += wi_s[it][k] * fi.x;  ri1 += wi_s[it][k] * fi.y;
        }
        float iso = 1.f / so, isi = 1.f / si;
        __half2 po = __floats2half2_rn(ro0 * iso, ro1 * iso);
        __half2 pi = __floats2half2_rn(ri0 * isi, ri1 * isi);
        reinterpret_cast<uint32_t*>(g_rout_h)[(nb + it) * 32 + dp] = as_u32(po);
        reinterpret_cast<uint32_t*>(g_rin_h)[(nb + it) * 32 + dp]  = as_u32(pi);
    }
}

// ---------------- main kernel: UNCHANGED from R13 (control, ~82 us) ------
#define SM_X   0
#define SM_W   (MROWS * PITCH_F)             // 17408
#define SM_AUX (SM_W + 128 * PITCH_F)        // 52224

struct Aux {
    uint32_t targ2[128];   // 256 halves, pre-scaled by 2^12
    float b1v[128];
    float w2v[128];
    float part[4][MROWS];
    float dots[MROWS];
    int   idxm[MROWS];
};
#define SMEM_TOTAL (SM_AUX + (int)sizeof(Aux))

__global__ __launch_bounds__(TBM, CTAS_SM)
void main_kernel(const int*   __restrict__ history,
                 const int*   __restrict__ target,
                 const float* __restrict__ b1,
                 const float* __restrict__ W2,
                 float*       __restrict__ out) {
    extern __shared__ char sm[];
    Aux* s = reinterpret_cast<Aux*>(sm + SM_AUX);
    const uint32_t sbase = smem_u32(sm);

    const int t    = threadIdx.x;
    const int wid  = t >> 5;
    const int lane = t & 31;

    const int m     = t >> 1;
    const int hhalf = t & 1;
    const bool rowvalid = (m < HIST);

    {
        uint4 z = make_uint4(0, 0, 0, 0);
        for (int i = t; i < MROWS * PITCH_F / 16; i += TBM)
            reinterpret_cast<uint4*>(sm + SM_X)[i] = z;
    }
    {
        const uint4* src = reinterpret_cast<const uint4*>(g_W8) + t * 16;
        char* dst = sm + SM_W + t * PITCH_F;
        #pragma unroll
        for (int g = 0; g < 16; g++)
            *reinterpret_cast<uint4*>(dst + g * 16) = src[g];
    }
    if (t < 128) { s->b1v[t] = b1[t]; s->w2v[t] = W2[t]; }
    __syncthreads();

    const int a_row0 = ((lane >> 3) & 1) * 8 + (lane & 7);
    const uint32_t a_addr0 = sbase + SM_X + a_row0 * PITCH_F + (lane >> 4) * 16;
    const int b_row = wid * 32 + (lane >> 4) * 8 + (lane & 7);
    const uint32_t b_addr0 = sbase + SM_W + b_row * PITCH_F + ((lane >> 3) & 1) * 16;

    const __half2 hscale = __floats2half2_rn(SCALE_X, SCALE_X);

    for (int p = blockIdx.x; p < BATCH; p += gridDim.x) {
        const int tg = target[p];

        if (t < 32) {
            const uint4* src;
            int woff;
            if (t < 16)      { src = reinterpret_cast<const uint4*>(g_Etarg_h + tg * 128) + t;       woff = t * 4; }
            else if (t < 24) { src = reinterpret_cast<const uint4*>(g_rout_h  + tg * 64) + (t - 16); woff = 64 + (t - 16) * 4; }
            else             { src = reinterpret_cast<const uint4*>(g_rin_h   + tg * 64) + (t - 24); woff = 96 + (t - 24) * 4; }
            uint4 u = *src;
            const uint32_t* up = reinterpret_cast<const uint32_t*>(&u);
            #pragma unroll
            for (int i = 0; i < 4; i++)
                s->targ2[woff + i] = as_u32(__hmul2(as_h2(up[i]), hscale));
        }
        int idx = 0;
        if (hhalf == 0 && rowvalid) idx = history[p * HIST + m];
        idx = __shfl_sync(0xffffffffu, idx, lane & ~1);
        if (hhalf == 0 && rowvalid) s->idxm[m] = idx;
        __syncthreads();

        __half2 acc = __floats2half2_rn(0.f, 0.f);
        if (rowvalid) {
            const uint32_t* tgp = &s->targ2[hhalf * 64];
            char* dst = sm + SM_X + m * PITCH_F + hhalf * 128;
            if (hhalf == 0) {
                const uint4* src = reinterpret_cast<const uint4*>(g_Ehist_h + idx * 128);
                #pragma unroll
                for (int g = 0; g < 8; g++)
                    mul16_h(src[2 * g], src[2 * g + 1], tgp + 8 * g, acc,
                            dst + 16 * g);
            } else {
                const uint4* s0 = reinterpret_cast<const uint4*>(g_rin_h  + idx * 64);
                const uint4* s1 = reinterpret_cast<const uint4*>(g_rout_h + idx * 64);
                #pragma unroll
                for (int g = 0; g < 4; g++)
                    mul16_h(s0[2 * g], s0[2 * g + 1], tgp + 8 * g, acc,
                            dst + 16 * g);
                #pragma unroll
                for (int g = 0; g < 4; g++)
                    mul16_h(s1[2 * g], s1[2 * g + 1], tgp + 32 + 8 * g, acc,
                            dst + 64 + 16 * g);
            }
        }
        float2 df = __half22float2(acc);
        float dot = (df.x + df.y) * INV_DOT;
        dot += __shfl_xor_sync(0xffffffffu, dot, 1);
        if (hhalf == 0 && rowvalid) s->dots[m] = dot;
        __syncthreads();

        float d[4][4][4];
        #pragma unroll
        for (int mf = 0; mf < 4; mf++)
            #pragma unroll
            for (int g = 0; g < 4; g++)
                #pragma unroll
                for (int i = 0; i < 4; i++) d[mf][g][i] = 0.f;

        #pragma unroll
        for (int ks = 0; ks < 8; ks++) {
            const uint32_t koff = ks * 32;
            uint32_t b0[4], b1r[4];
            ldmatrix_x4(b0[0], b0[1], b0[2], b0[3], b_addr0 + koff);
            ldmatrix_x4(b1r[0], b1r[1], b1r[2], b1r[3],
                        b_addr0 + 16 * PITCH_F + koff);
            #pragma unroll
            for (int mf = 0; mf < 4; mf++) {
                uint32_t a[4];
                ldmatrix_x4(a[0], a[1], a[2], a[3],
                            a_addr0 + mf * 16 * PITCH_F + koff);
                mma_fp8(d[mf][0][0], d[mf][0][1], d[mf][0][2], d[mf][0][3],
                        a[0], a[1], a[2], a[3], b0[0], b0[1]);
                mma_fp8(d[mf][1][0], d[mf][1][1], d[mf][1][2], d[mf][1][3],
                        a[0], a[1], a[2], a[3], b0[2], b0[3]);
                mma_fp8(d[mf][2][0], d[mf][2][1], d[mf][2][2], d[mf][2][3],
                        a[0], a[1], a[2], a[3], b1r[0], b1r[1]);
                mma_fp8(d[mf][3][0], d[mf][3][1], d[mf][3][2], d[mf][3][3],
                        a[0], a[1], a[2], a[3], b1r[2], b1r[3]);
            }
        }

        {
            float acc2[4][2];
            #pragma unroll
            for (int mf = 0; mf < 4; mf++) { acc2[mf][0] = 0.f; acc2[mf][1] = 0.f; }
            #pragma unroll
            for (int g = 0; g < 4; g++) {
                const int c0 = wid * 32 + g * 8 + 2 * (lane & 3);
                const float bb0 = s->b1v[c0], bb1 = s->b1v[c0 + 1];
                const float ww0 = s->w2v[c0], ww1 = s->w2v[c0 + 1];
                #pragma unroll
                for (int mf = 0; mf < 4; mf++) {
                    acc2[mf][0] += fmaxf(fmaf(d[mf][g][0], INV_SCALE, bb0), 0.f) * ww0
                                 + fmaxf(fmaf(d[mf][g][1], INV_SCALE, bb1), 0.f) * ww1;
                    acc2[mf][1] += fmaxf(fmaf(d[mf][g][2], INV_SCALE, bb0), 0.f) * ww0
                                 + fmaxf(fmaf(d[mf][g][3], INV_SCALE, bb1), 0.f) * ww1;
                }
            }
            #pragma unroll
            for (int mf = 0; mf < 4; mf++) {
                #pragma unroll
                for (int i = 0; i < 2; i++) {
                    acc2[mf][i] += __shfl_xor_sync(0xffffffffu, acc2[mf][i], 1);
                    acc2[mf][i] += __shfl_xor_sync(0xffffffffu, acc2[mf][i], 2);
                }
            }
            if ((lane & 3) == 0) {
                #pragma unroll
                for (int mf = 0; mf < 4; mf++) {
                    const int row = mf * 16 + (lane >> 2);
                    s->part[wid][row]     = acc2[mf][0];
                    s->part[wid][row + 8] = acc2[mf][1];
                }
            }
        }
        __syncthreads();

        if (wid == 0) {
            float num = 0.f, den = 0.f;
            #pragma unroll
            for (int it = 0; it < 2; it++) {
                int hh = lane + it * 32;
                if (hh < HIST) {
                    float sc = (s->part[0][hh] + s->part[1][hh]) +
                               (s->part[2][hh] + s->part[3][hh]);
                    float e = expf(sc);
                    if (s->idxm[hh] == tg) e = 0.f;
                    num += e * s->dots[hh];
                    den += e;
                }
            }
            #pragma unroll
            for (int o = 16; o; o >>= 1) {
                num += __shfl_xor_sync(0xffffffffu, num, o);
                den += __shfl_xor_sync(0xffffffffu, den, o);
            }
            if (lane == 0) {
                float pred = num / sqrtf(den);     // BETA = 0.5
                out[p] = 1.f / (1.f + expf(-pred));
            }
        }
        __syncthreads();
    }
}

// ---------------- launch ----------------
extern "C" void kernel_launch(void* const* d_in, const int* in_sizes, int n_in,
                              void* d_out, int out_size) {
    const int*   history = (const int*)  d_in[0];
    const int*   target  = (const int*)  d_in[1];
    const int*   near_p  = (const int*)  d_in[2];
    const float* E_in    = (const float*)d_in[4];
    const float* E_out   = (const float*)d_in[5];
    const float* E_hist  = (const float*)d_in[6];
    const float* E_targ  = (const float*)d_in[7];
    const float* W1      = (const float*)d_in[8];
    const float* b1      = (const float*)d_in[9];
    const float* W2      = (const float*)d_in[10];
    float* out = (float*)d_out;

    conv1_kernel<<<1184, 256>>>(E_in, E_out);
    prep2_kernel<<<PREP2_GRID, 256>>>(near_p, E_hist, E_targ, W1);

    cudaFuncSetAttribute(main_kernel,
                         cudaFuncAttributeMaxDynamicSharedMemorySize,
                         SMEM_TOTAL);
    main_kernel<<<GRIDM, TBM, SMEM_TOTAL>>>(history, target, b1, W2, out);
}